// round 1
// baseline (speedup 1.0000x reference)
#include <cuda_runtime.h>
#include <cstdint>

#define HW   4096
#define CIN  256
#define CMID 128
#define NB   4

// ---------------- scratch (static __device__, no allocation) ----------------
__device__ float g_q [NB*CMID*HW];   // [n][c][t]
__device__ float g_k [NB*CMID*HW];   // [n][c][s]
__device__ float g_vT[NB*HW*CMID];   // [n][s][c]  (transposed for PV gemm)
__device__ float g_z [NB*CMID*HW];   // [n][c][t]

// ---------------- threefry2x32 (JAX partitionable path) ----------------
// key = (0, 42); count = flat index f (hi word = 0 since f < 2^32)
// bits = out0 ^ out1 ; uniform<0.1  <=>  (bits>>9) < 838861
__device__ __forceinline__ uint32_t thf_bits(uint32_t f) {
    const uint32_t K0 = 0u;
    const uint32_t K1 = 42u;
    const uint32_t K2 = 0x1BD11BDAu ^ 42u;
    uint32_t x0 = 0u + K0;
    uint32_t x1 = f  + K1;
#define THF_R(r) { x0 += x1; x1 = __funnelshift_l(x1, x1, (r)); x1 ^= x0; }
    THF_R(13) THF_R(15) THF_R(26) THF_R(6)   x0 += K1; x1 += K2 + 1u;
    THF_R(17) THF_R(29) THF_R(16) THF_R(24)  x0 += K2; x1 += K0 + 2u;
    THF_R(13) THF_R(15) THF_R(26) THF_R(6)   x0 += K0; x1 += K1 + 3u;
    THF_R(17) THF_R(29) THF_R(16) THF_R(24)  x0 += K1; x1 += K2 + 4u;
    THF_R(13) THF_R(15) THF_R(26) THF_R(6)   x0 += K2; x1 += K0 + 5u;
#undef THF_R
    return x0 ^ x1;
}

// ---------------- kernel 1: fused q/k/v projection ----------------
// grid (32 t-tiles, 4 n, 3 mats), block 256. out tile: 128(o) x 128(t)
__global__ void __launch_bounds__(256)
k_qkv(const float* __restrict__ x,
      const float* __restrict__ wq, const float* __restrict__ bq,
      const float* __restrict__ wk, const float* __restrict__ bk,
      const float* __restrict__ wv, const float* __restrict__ bv)
{
    extern __shared__ float sm[];
    float* Xs = sm;            // [64][128]
    float* Ws = sm + 8192;     // [64][129]  WsT[cc][o], padded

    const int tid = threadIdx.x;
    const int tx = tid & 15, ty = tid >> 4;
    const int t0 = blockIdx.x * 128;
    const int n  = blockIdx.y;
    const int m  = blockIdx.z;
    const float* w = (m == 0) ? wq : (m == 1) ? wk : wv;
    const float* b = (m == 0) ? bq : (m == 1) ? bk : bv;

    float acc[8][8];
#pragma unroll
    for (int i = 0; i < 8; i++)
#pragma unroll
        for (int j = 0; j < 8; j++) acc[i][j] = 0.f;

    for (int c0 = 0; c0 < CIN; c0 += 64) {
        __syncthreads();
        for (int i = tid; i < 64*32; i += 256) {           // Xs: 64 rows x 32 float4
            int cc = i >> 5, t4 = i & 31;
            *(float4*)(Xs + cc*128 + t4*4) =
                *(const float4*)(x + (size_t)(n*CIN + c0 + cc)*HW + t0 + t4*4);
        }
        for (int i = tid; i < 128*64; i += 256) {          // WsT
            int o = i >> 6, cc = i & 63;
            Ws[cc*129 + o] = w[o*CIN + c0 + cc];
        }
        __syncthreads();
#pragma unroll 8
        for (int cc = 0; cc < 64; cc++) {
            float a[8], bb[8];
#pragma unroll
            for (int i = 0; i < 8; i++) a[i] = Ws[cc*129 + ty*8 + i];
            float4 b0 = *(const float4*)(Xs + cc*128 + tx*8);
            float4 b1 = *(const float4*)(Xs + cc*128 + tx*8 + 4);
            bb[0]=b0.x; bb[1]=b0.y; bb[2]=b0.z; bb[3]=b0.w;
            bb[4]=b1.x; bb[5]=b1.y; bb[6]=b1.z; bb[7]=b1.w;
#pragma unroll
            for (int i = 0; i < 8; i++)
#pragma unroll
                for (int j = 0; j < 8; j++) acc[i][j] += a[i]*bb[j];
        }
    }

    if (m < 2) {
        float* g = (m == 0) ? g_q : g_k;
#pragma unroll
        for (int i = 0; i < 8; i++) {
            int o = ty*8 + i; float bias = b[o];
            float* row = g + (size_t)(n*CMID + o)*HW + t0 + tx*8;
            float4 r0 = make_float4(acc[i][0]+bias, acc[i][1]+bias, acc[i][2]+bias, acc[i][3]+bias);
            float4 r1 = make_float4(acc[i][4]+bias, acc[i][5]+bias, acc[i][6]+bias, acc[i][7]+bias);
            *(float4*)row = r0; *(float4*)(row + 4) = r1;
        }
    } else {
#pragma unroll
        for (int i = 0; i < 8; i++) {
            int o = ty*8 + i; float bias = b[o];
#pragma unroll
            for (int j = 0; j < 8; j++) {
                int t = t0 + tx*8 + j;
                g_vT[(size_t)(n*HW + t)*CMID + o] = acc[i][j] + bias;
            }
        }
    }
}

// ---------------- kernel 2: fused attention (mask + softmax + PV) ----------------
// grid (64 t-tiles of 64, 4 n), block 256
__global__ void __launch_bounds__(256)
k_attn()
{
    extern __shared__ float sm[];
    float* Qs  = sm;                 // [128][64]  q[c][t]
    float* Ks  = sm + 8192;          // [128][64]  k[c][s]
    float* VsT = sm + 16384;         // [64][128]  v[s][c]
    float* PsT = sm + 24576;         // [64][65]   p[s][t], padded
    float* dsh = sm + 24576 + 64*65; // [64] row denominators

    const int tid = threadIdx.x;
    const int tx = tid & 15, ty = tid >> 4;
    const int t0 = blockIdx.x * 64;
    const int n  = blockIdx.y;

    for (int i = tid; i < 128*16; i += 256) {
        int c = i >> 4, t4 = i & 15;
        *(float4*)(Qs + c*64 + t4*4) =
            *(const float4*)(g_q + (size_t)(n*CMID + c)*HW + t0 + t4*4);
    }
    if (tid < 64) dsh[tid] = 0.f;

    float acc2[8][4];
#pragma unroll
    for (int i = 0; i < 8; i++)
#pragma unroll
        for (int j = 0; j < 4; j++) acc2[i][j] = 0.f;
    float dsum[4] = {0.f, 0.f, 0.f, 0.f};

    for (int s0 = 0; s0 < HW; s0 += 64) {
        __syncthreads();                       // prev iter done with Ks/VsT/PsT
        for (int i = tid; i < 128*16; i += 256) {
            int c = i >> 4, s4 = i & 15;
            *(float4*)(Ks + c*64 + s4*4) =
                *(const float4*)(g_k + (size_t)(n*CMID + c)*HW + s0 + s4*4);
        }
        for (int i = tid; i < 64*32; i += 256) {
            int s = i >> 5, c4 = i & 31;
            *(float4*)(VsT + s*128 + c4*4) =
                *(const float4*)(g_vT + (size_t)(n*HW + s0 + s)*CMID + c4*4);
        }
        __syncthreads();

        // GEMM1: S[t][s] = sum_c Q[c][t] K[c][s]; micro 4x4 at (ty*4, tx*4)
        float a1[4][4];
#pragma unroll
        for (int i = 0; i < 4; i++)
#pragma unroll
            for (int j = 0; j < 4; j++) a1[i][j] = 0.f;
#pragma unroll 8
        for (int c = 0; c < 128; c++) {
            float4 q4 = *(const float4*)(Qs + c*64 + (ty<<2));
            float4 k4 = *(const float4*)(Ks + c*64 + (tx<<2));
            float qa[4] = {q4.x, q4.y, q4.z, q4.w};
            float kb[4] = {k4.x, k4.y, k4.z, k4.w};
#pragma unroll
            for (int i = 0; i < 4; i++)
#pragma unroll
                for (int j = 0; j < 4; j++) a1[i][j] += qa[i]*kb[j];
        }

        // mask (inline threefry) + exp + stage P^T
        uint32_t fbase = ((uint32_t)n << 24) + (uint32_t)(t0 + (ty<<2))*4096u
                       + (uint32_t)(s0 + (tx<<2));
#pragma unroll
        for (int i = 0; i < 4; i++) {
#pragma unroll
            for (int j = 0; j < 4; j++) {
                uint32_t bits = thf_bits(fbase + (uint32_t)i*4096u + (uint32_t)j);
                float p = ((bits >> 9) < 838861u) ? 0.f
                                                  : __expf(a1[i][j] * 0.015625f);
                PsT[(tx*4 + j)*65 + ty*4 + i] = p;
                dsum[i] += p;
            }
        }
        __syncthreads();

        // GEMM2: acc[c][t] += sum_s V[s][c] P[s][t]; micro 8(c) x 4(t)
#pragma unroll 4
        for (int s = 0; s < 64; s++) {
            float4 v0 = *(const float4*)(VsT + s*128 + (tx<<3));
            float4 v1 = *(const float4*)(VsT + s*128 + (tx<<3) + 4);
            float va[8] = {v0.x, v0.y, v0.z, v0.w, v1.x, v1.y, v1.z, v1.w};
            float pb[4];
#pragma unroll
            for (int j = 0; j < 4; j++) pb[j] = PsT[s*65 + (ty<<2) + j];
#pragma unroll
            for (int i = 0; i < 8; i++)
#pragma unroll
                for (int j = 0; j < 4; j++) acc2[i][j] += va[i]*pb[j];
        }
    }

    // reduce row denominators across tx, then normalize + write z
#pragma unroll
    for (int i = 0; i < 4; i++) atomicAdd(&dsh[ty*4 + i], dsum[i]);
    __syncthreads();
#pragma unroll
    for (int j = 0; j < 4; j++) {
        float inv = 1.f / dsh[(ty<<2) + j];
#pragma unroll
        for (int i = 0; i < 8; i++) {
            int c = (tx<<3) + i;
            g_z[(size_t)(n*CMID + c)*HW + t0 + (ty<<2) + j] = acc2[i][j] * inv;
        }
    }
}

// ---------------- kernel 3: output projection + residual ----------------
// grid (32 t-tiles of 128, 4 n, 2 o-halves), block 256
__global__ void __launch_bounds__(256)
k_out(const float* __restrict__ x, const float* __restrict__ wz,
      const float* __restrict__ bz, float* __restrict__ out)
{
    extern __shared__ float sm[];
    float* Zs = sm;            // [64][128]
    float* Ws = sm + 8192;     // [64][129]

    const int tid = threadIdx.x;
    const int tx = tid & 15, ty = tid >> 4;
    const int t0 = blockIdx.x * 128;
    const int n  = blockIdx.y;
    const int o0 = blockIdx.z * 128;

    float acc[8][8];
#pragma unroll
    for (int i = 0; i < 8; i++)
#pragma unroll
        for (int j = 0; j < 8; j++) acc[i][j] = 0.f;

    for (int c0 = 0; c0 < CMID; c0 += 64) {
        __syncthreads();
        for (int i = tid; i < 64*32; i += 256) {
            int cc = i >> 5, t4 = i & 31;
            *(float4*)(Zs + cc*128 + t4*4) =
                *(const float4*)(g_z + (size_t)(n*CMID + c0 + cc)*HW + t0 + t4*4);
        }
        for (int i = tid; i < 128*64; i += 256) {
            int o = i >> 6, cc = i & 63;
            Ws[cc*129 + o] = wz[(o0 + o)*CMID + c0 + cc];
        }
        __syncthreads();
#pragma unroll 8
        for (int cc = 0; cc < 64; cc++) {
            float a[8], bb[8];
#pragma unroll
            for (int i = 0; i < 8; i++) a[i] = Ws[cc*129 + ty*8 + i];
            float4 b0 = *(const float4*)(Zs + cc*128 + tx*8);
            float4 b1 = *(const float4*)(Zs + cc*128 + tx*8 + 4);
            bb[0]=b0.x; bb[1]=b0.y; bb[2]=b0.z; bb[3]=b0.w;
            bb[4]=b1.x; bb[5]=b1.y; bb[6]=b1.z; bb[7]=b1.w;
#pragma unroll
            for (int i = 0; i < 8; i++)
#pragma unroll
                for (int j = 0; j < 8; j++) acc[i][j] += a[i]*bb[j];
        }
    }

#pragma unroll
    for (int i = 0; i < 8; i++) {
        int o = o0 + ty*8 + i;
        float bias = bz[o];
        const float* xr = x   + (size_t)(n*CIN + o)*HW + t0 + tx*8;
        float*       orow = out + (size_t)(n*CIN + o)*HW + t0 + tx*8;
        float4 x0 = *(const float4*)xr;
        float4 x1 = *(const float4*)(xr + 4);
        float4 r0 = make_float4(x0.x + acc[i][0] + bias, x0.y + acc[i][1] + bias,
                                x0.z + acc[i][2] + bias, x0.w + acc[i][3] + bias);
        float4 r1 = make_float4(x1.x + acc[i][4] + bias, x1.y + acc[i][5] + bias,
                                x1.z + acc[i][6] + bias, x1.w + acc[i][7] + bias);
        *(float4*)orow = r0; *(float4*)(orow + 4) = r1;
    }
}

// ---------------- launcher ----------------
extern "C" void kernel_launch(void* const* d_in, const int* in_sizes, int n_in,
                              void* d_out, int out_size)
{
    const float* x  = (const float*)d_in[0];
    const float* wq = (const float*)d_in[1];
    const float* bq = (const float*)d_in[2];
    const float* wk = (const float*)d_in[3];
    const float* bk = (const float*)d_in[4];
    const float* wv = (const float*)d_in[5];
    const float* bv = (const float*)d_in[6];
    const float* wz = (const float*)d_in[7];
    const float* bz = (const float*)d_in[8];
    float* out = (float*)d_out;

    const int SM_PROJ = (8192 + 64*129) * 4;                  // 65792 B
    const int SM_ATTN = (8192 + 8192 + 8192 + 64*65 + 64)*4;  // 115200 B

    cudaFuncSetAttribute(k_qkv,  cudaFuncAttributeMaxDynamicSharedMemorySize, SM_PROJ);
    cudaFuncSetAttribute(k_attn, cudaFuncAttributeMaxDynamicSharedMemorySize, SM_ATTN);
    cudaFuncSetAttribute(k_out,  cudaFuncAttributeMaxDynamicSharedMemorySize, SM_PROJ);

    k_qkv <<<dim3(32, 4, 3), 256, SM_PROJ>>>(x, wq, bq, wk, bk, wv, bv);
    k_attn<<<dim3(64, 4),    256, SM_ATTN>>>();
    k_out <<<dim3(32, 4, 2), 256, SM_PROJ>>>(x, wz, bz, out);
}

// round 2
// speedup vs baseline: 4.9304x; 4.9304x over previous
#include <cuda_runtime.h>
#include <cuda_bf16.h>
#include <cstdint>

#define HW   4096
#define CIN  256
#define CMID 128
#define NB   4

// ---------------- scratch ----------------
__device__ __nv_bfloat16 g_qT[NB*HW*CMID];   // [n][t][c]
__device__ __nv_bfloat16 g_kT[NB*HW*CMID];   // [n][s][c]
__device__ __nv_bfloat16 g_vT[NB*HW*CMID];   // [n][s][c]
__device__ float         g_z [NB*CMID*HW];   // [n][c][t]

// ---------------- threefry2x32 (JAX partitionable) ----------------
__device__ __forceinline__ uint32_t thf_bits(uint32_t f) {
    const uint32_t K0 = 0u;
    const uint32_t K1 = 42u;
    const uint32_t K2 = 0x1BD11BDAu ^ 42u;
    uint32_t x0 = 0u + K0;
    uint32_t x1 = f  + K1;
#define THF_R(r) { x0 += x1; x1 = __funnelshift_l(x1, x1, (r)); x1 ^= x0; }
    THF_R(13) THF_R(15) THF_R(26) THF_R(6)   x0 += K1; x1 += K2 + 1u;
    THF_R(17) THF_R(29) THF_R(16) THF_R(24)  x0 += K2; x1 += K0 + 2u;
    THF_R(13) THF_R(15) THF_R(26) THF_R(6)   x0 += K0; x1 += K1 + 3u;
    THF_R(17) THF_R(29) THF_R(16) THF_R(24)  x0 += K1; x1 += K2 + 4u;
    THF_R(13) THF_R(15) THF_R(26) THF_R(6)   x0 += K2; x1 += K0 + 5u;
#undef THF_R
    return x0 ^ x1;
}

// ---------------- helpers ----------------
__device__ __forceinline__ void cp16(void* dst, const void* src) {
    uint32_t d = (uint32_t)__cvta_generic_to_shared(dst);
    asm volatile("cp.async.cg.shared.global [%0], [%1], 16;\n" :: "r"(d), "l"(src));
}
__device__ __forceinline__ void ldsm_x4(uint32_t& a0, uint32_t& a1, uint32_t& a2, uint32_t& a3, const void* p) {
    uint32_t s = (uint32_t)__cvta_generic_to_shared(p);
    asm volatile("ldmatrix.sync.aligned.m8n8.x4.shared.b16 {%0,%1,%2,%3}, [%4];\n"
                 : "=r"(a0), "=r"(a1), "=r"(a2), "=r"(a3) : "r"(s));
}
__device__ __forceinline__ void ldsm_x2(uint32_t& b0, uint32_t& b1, const void* p) {
    uint32_t s = (uint32_t)__cvta_generic_to_shared(p);
    asm volatile("ldmatrix.sync.aligned.m8n8.x2.shared.b16 {%0,%1}, [%2];\n"
                 : "=r"(b0), "=r"(b1) : "r"(s));
}
__device__ __forceinline__ void ldsm_x2t(uint32_t& b0, uint32_t& b1, const void* p) {
    uint32_t s = (uint32_t)__cvta_generic_to_shared(p);
    asm volatile("ldmatrix.sync.aligned.m8n8.x2.trans.shared.b16 {%0,%1}, [%2];\n"
                 : "=r"(b0), "=r"(b1) : "r"(s));
}
__device__ __forceinline__ void mma16816(float* d, uint32_t a0, uint32_t a1, uint32_t a2, uint32_t a3,
                                         uint32_t b0, uint32_t b1) {
    asm volatile("mma.sync.aligned.m16n8k16.row.col.f32.bf16.bf16.f32 "
                 "{%0,%1,%2,%3}, {%4,%5,%6,%7}, {%8,%9}, {%0,%1,%2,%3};\n"
                 : "+f"(d[0]), "+f"(d[1]), "+f"(d[2]), "+f"(d[3])
                 : "r"(a0), "r"(a1), "r"(a2), "r"(a3), "r"(b0), "r"(b1));
}
__device__ __forceinline__ uint32_t pack_bf2(float lo, float hi) {
    __nv_bfloat162 h = __floats2bfloat162_rn(lo, hi);   // .x = lo, .y = hi
    return *(uint32_t*)&h;
}

// ---------------- kernel 1: fused q/k/v projection (fp32 compute, bf16 T output) ----------------
__global__ void __launch_bounds__(256)
k_qkv(const float* __restrict__ x,
      const float* __restrict__ wq, const float* __restrict__ bq,
      const float* __restrict__ wk, const float* __restrict__ bk,
      const float* __restrict__ wv, const float* __restrict__ bv)
{
    extern __shared__ float sm[];
    float* Xs = sm;            // [64][128]
    float* Ws = sm + 8192;     // [64][129]

    const int tid = threadIdx.x;
    const int tx = tid & 15, ty = tid >> 4;
    const int t0 = blockIdx.x * 128;
    const int n  = blockIdx.y;
    const int m  = blockIdx.z;
    const float* w = (m == 0) ? wq : (m == 1) ? wk : wv;
    const float* b = (m == 0) ? bq : (m == 1) ? bk : bv;

    float acc[8][8];
#pragma unroll
    for (int i = 0; i < 8; i++)
#pragma unroll
        for (int j = 0; j < 8; j++) acc[i][j] = 0.f;

    for (int c0 = 0; c0 < CIN; c0 += 64) {
        __syncthreads();
        for (int i = tid; i < 64*32; i += 256) {
            int cc = i >> 5, t4 = i & 31;
            *(float4*)(Xs + cc*128 + t4*4) =
                *(const float4*)(x + (size_t)(n*CIN + c0 + cc)*HW + t0 + t4*4);
        }
        for (int i = tid; i < 128*64; i += 256) {
            int o = i >> 6, cc = i & 63;
            Ws[cc*129 + o] = w[o*CIN + c0 + cc];
        }
        __syncthreads();
#pragma unroll 8
        for (int cc = 0; cc < 64; cc++) {
            float a[8], bb[8];
#pragma unroll
            for (int i = 0; i < 8; i++) a[i] = Ws[cc*129 + ty*8 + i];
            float4 b0 = *(const float4*)(Xs + cc*128 + tx*8);
            float4 b1 = *(const float4*)(Xs + cc*128 + tx*8 + 4);
            bb[0]=b0.x; bb[1]=b0.y; bb[2]=b0.z; bb[3]=b0.w;
            bb[4]=b1.x; bb[5]=b1.y; bb[6]=b1.z; bb[7]=b1.w;
#pragma unroll
            for (int i = 0; i < 8; i++)
#pragma unroll
                for (int j = 0; j < 8; j++) acc[i][j] += a[i]*bb[j];
        }
    }

    // stage transposed bf16 [t][c] then write coalesced
    __syncthreads();
    __nv_bfloat16* Tb = (__nv_bfloat16*)sm;   // [128][136]
#pragma unroll
    for (int i = 0; i < 8; i++) {
        float bias = b[ty*8 + i];
#pragma unroll
        for (int j = 0; j < 8; j++)
            Tb[(tx*8 + j)*136 + ty*8 + i] = __float2bfloat16(acc[i][j] + bias);
    }
    __syncthreads();
    __nv_bfloat16* g = (m == 0) ? g_qT : (m == 1) ? g_kT : g_vT;
    for (int i = tid; i < 128*16; i += 256) {
        int row = i >> 4, ch = i & 15;
        *(uint4*)(g + (size_t)(n*HW + t0 + row)*CMID + ch*8) =
            *(const uint4*)(Tb + row*136 + ch*8);
    }
}

// ---------------- kernel 2: tensor-core attention ----------------
// block 256 (8 warps, each owns 16 t-rows), t-tile 128, s-tile 64, grid (32, 4)
#define ATTN_SMEM 104448
__global__ void __launch_bounds__(256, 1)
k_attn()
{
    extern __shared__ char sm8[];
    __nv_bfloat16* Qs = (__nv_bfloat16*)sm8;                      // [128][136]
    __nv_bfloat16* Kb0 = (__nv_bfloat16*)(sm8 + 34816);           // [64][136]
    __nv_bfloat16* Vb0 = (__nv_bfloat16*)(sm8 + 52224);
    __nv_bfloat16* Kb1 = (__nv_bfloat16*)(sm8 + 69632);
    __nv_bfloat16* Vb1 = (__nv_bfloat16*)(sm8 + 87040);

    const int tid = threadIdx.x, lane = tid & 31, w = tid >> 5;
    const int t0 = blockIdx.x * 128, n = blockIdx.y;
    const int g = lane >> 2, tg = lane & 3;

    // Q tile + s-tile 0 → group 0
    for (int i = tid; i < 128*16; i += 256) {
        int r = i >> 4, ch = i & 15;
        cp16(Qs + r*136 + ch*8, g_qT + (size_t)(n*HW + t0 + r)*CMID + ch*8);
    }
    for (int i = tid; i < 64*16; i += 256) {
        int r = i >> 4, ch = i & 15;
        size_t go = (size_t)(n*HW + r)*CMID + ch*8;
        cp16(Kb0 + r*136 + ch*8, g_kT + go);
        cp16(Vb0 + r*136 + ch*8, g_vT + go);
    }
    asm volatile("cp.async.commit_group;\n");

    float Z[16][4];
#pragma unroll
    for (int jc = 0; jc < 16; jc++)
#pragma unroll
        for (int q = 0; q < 4; q++) Z[jc][q] = 0.f;
    float dsum0 = 0.f, dsum1 = 0.f;

    for (int it = 0; it < 64; it++) {
        const __nv_bfloat16* K_ = (it & 1) ? Kb1 : Kb0;
        const __nv_bfloat16* V_ = (it & 1) ? Vb1 : Vb0;
        if (it + 1 < 64) {
            __nv_bfloat16* Kn = ((it+1) & 1) ? Kb1 : Kb0;
            __nv_bfloat16* Vn = ((it+1) & 1) ? Vb1 : Vb0;
            int s0n = (it + 1) * 64;
            for (int i = tid; i < 64*16; i += 256) {
                int r = i >> 4, ch = i & 15;
                size_t go = (size_t)(n*HW + s0n + r)*CMID + ch*8;
                cp16(Kn + r*136 + ch*8, g_kT + go);
                cp16(Vn + r*136 + ch*8, g_vT + go);
            }
            asm volatile("cp.async.commit_group;\n");
            asm volatile("cp.async.wait_group 1;\n");
        } else {
            asm volatile("cp.async.wait_group 0;\n");
        }
        __syncthreads();

        // ---- GEMM1: S[16t x 64s] = Q[t][c] * K^T ----
        float S[8][4];
#pragma unroll
        for (int j = 0; j < 8; j++)
#pragma unroll
            for (int q = 0; q < 4; q++) S[j][q] = 0.f;

#pragma unroll
        for (int kk = 0; kk < 8; kk++) {
            uint32_t a0, a1, a2, a3;
            ldsm_x4(a0, a1, a2, a3,
                    Qs + (w*16 + (lane & 15))*136 + kk*16 + (lane >> 4)*8);
#pragma unroll
            for (int j = 0; j < 8; j++) {
                uint32_t b0, b1;
                ldsm_x2(b0, b1,
                        K_ + (j*8 + (lane & 7))*136 + kk*16 + ((lane >> 3) & 1)*8);
                mma16816(S[j], a0, a1, a2, a3, b0, b1);
            }
        }

        // ---- mask + exp (threefry fused) ----
        const int s0 = it * 64;
        const uint32_t fb0 = ((uint32_t)n << 24) + (uint32_t)(t0 + w*16 + g)*4096u
                           + (uint32_t)(s0 + tg*2);
        const uint32_t fb1 = fb0 + 8u*4096u;
#pragma unroll
        for (int j = 0; j < 8; j++) {
            uint32_t f0 = fb0 + (uint32_t)(j*8);
            uint32_t f1 = fb1 + (uint32_t)(j*8);
            S[j][0] = ((thf_bits(f0)     >> 9) < 838861u) ? 0.f : __expf(S[j][0]*0.015625f);
            S[j][1] = ((thf_bits(f0+1u)  >> 9) < 838861u) ? 0.f : __expf(S[j][1]*0.015625f);
            S[j][2] = ((thf_bits(f1)     >> 9) < 838861u) ? 0.f : __expf(S[j][2]*0.015625f);
            S[j][3] = ((thf_bits(f1+1u)  >> 9) < 838861u) ? 0.f : __expf(S[j][3]*0.015625f);
            dsum0 += S[j][0] + S[j][1];
            dsum1 += S[j][2] + S[j][3];
        }

        // ---- GEMM2: Z[16t x 128c] += P[t][s] * V[s][c] ----
#pragma unroll
        for (int m = 0; m < 4; m++) {
            uint32_t pa0 = pack_bf2(S[2*m][0],   S[2*m][1]);
            uint32_t pa1 = pack_bf2(S[2*m][2],   S[2*m][3]);
            uint32_t pa2 = pack_bf2(S[2*m+1][0], S[2*m+1][1]);
            uint32_t pa3 = pack_bf2(S[2*m+1][2], S[2*m+1][3]);
#pragma unroll
            for (int jc = 0; jc < 16; jc++) {
                uint32_t b0, b1;
                ldsm_x2t(b0, b1,
                         V_ + (m*16 + (lane & 7) + ((lane >> 3) & 1)*8)*136 + jc*8);
                mma16816(Z[jc], pa0, pa1, pa2, pa3, b0, b1);
            }
        }
        __syncthreads();   // protect buffers before next prefetch overwrite
    }

    // ---- row-sum reduce across quad lanes ----
    dsum0 += __shfl_xor_sync(0xffffffffu, dsum0, 1);
    dsum0 += __shfl_xor_sync(0xffffffffu, dsum0, 2);
    dsum1 += __shfl_xor_sync(0xffffffffu, dsum1, 1);
    dsum1 += __shfl_xor_sync(0xffffffffu, dsum1, 2);
    const float inv0 = 1.f / dsum0, inv1 = 1.f / dsum1;

    // ---- stage z[t][c] in smem, write g_z[c][t] coalesced ----
    float* zb = (float*)(sm8 + 34816);   // [128][133]
#pragma unroll
    for (int jc = 0; jc < 16; jc++) {
        int c = jc*8 + tg*2;
        zb[(w*16 + g)*133 + c]       = Z[jc][0] * inv0;
        zb[(w*16 + g)*133 + c + 1]   = Z[jc][1] * inv0;
        zb[(w*16 + g + 8)*133 + c]     = Z[jc][2] * inv1;
        zb[(w*16 + g + 8)*133 + c + 1] = Z[jc][3] * inv1;
    }
    __syncthreads();
    for (int i = tid; i < 128*32; i += 256) {
        int c = i >> 5, ch = i & 31;
        int tt = ch * 4;
        float4 v;
        v.x = zb[(tt+0)*133 + c];
        v.y = zb[(tt+1)*133 + c];
        v.z = zb[(tt+2)*133 + c];
        v.w = zb[(tt+3)*133 + c];
        *(float4*)(g_z + (size_t)(n*CMID + c)*HW + t0 + tt) = v;
    }
}

// ---------------- kernel 3: output projection + residual ----------------
__global__ void __launch_bounds__(256)
k_out(const float* __restrict__ x, const float* __restrict__ wz,
      const float* __restrict__ bz, float* __restrict__ out)
{
    extern __shared__ float sm[];
    float* Zs = sm;            // [64][128]
    float* Ws = sm + 8192;     // [64][129]

    const int tid = threadIdx.x;
    const int tx = tid & 15, ty = tid >> 4;
    const int t0 = blockIdx.x * 128;
    const int n  = blockIdx.y;
    const int o0 = blockIdx.z * 128;

    float acc[8][8];
#pragma unroll
    for (int i = 0; i < 8; i++)
#pragma unroll
        for (int j = 0; j < 8; j++) acc[i][j] = 0.f;

    for (int c0 = 0; c0 < CMID; c0 += 64) {
        __syncthreads();
        for (int i = tid; i < 64*32; i += 256) {
            int cc = i >> 5, t4 = i & 31;
            *(float4*)(Zs + cc*128 + t4*4) =
                *(const float4*)(g_z + (size_t)(n*CMID + c0 + cc)*HW + t0 + t4*4);
        }
        for (int i = tid; i < 128*64; i += 256) {
            int o = i >> 6, cc = i & 63;
            Ws[cc*129 + o] = wz[(o0 + o)*CMID + c0 + cc];
        }
        __syncthreads();
#pragma unroll 8
        for (int cc = 0; cc < 64; cc++) {
            float a[8], bb[8];
#pragma unroll
            for (int i = 0; i < 8; i++) a[i] = Ws[cc*129 + ty*8 + i];
            float4 b0 = *(const float4*)(Zs + cc*128 + tx*8);
            float4 b1 = *(const float4*)(Zs + cc*128 + tx*8 + 4);
            bb[0]=b0.x; bb[1]=b0.y; bb[2]=b0.z; bb[3]=b0.w;
            bb[4]=b1.x; bb[5]=b1.y; bb[6]=b1.z; bb[7]=b1.w;
#pragma unroll
            for (int i = 0; i < 8; i++)
#pragma unroll
                for (int j = 0; j < 8; j++) acc[i][j] += a[i]*bb[j];
        }
    }

#pragma unroll
    for (int i = 0; i < 8; i++) {
        int o = o0 + ty*8 + i;
        float bias = bz[o];
        const float* xr  = x   + (size_t)(n*CIN + o)*HW + t0 + tx*8;
        float*       orow = out + (size_t)(n*CIN + o)*HW + t0 + tx*8;
        float4 x0 = *(const float4*)xr;
        float4 x1 = *(const float4*)(xr + 4);
        float4 r0 = make_float4(x0.x + acc[i][0] + bias, x0.y + acc[i][1] + bias,
                                x0.z + acc[i][2] + bias, x0.w + acc[i][3] + bias);
        float4 r1 = make_float4(x1.x + acc[i][4] + bias, x1.y + acc[i][5] + bias,
                                x1.z + acc[i][6] + bias, x1.w + acc[i][7] + bias);
        *(float4*)orow = r0; *(float4*)(orow + 4) = r1;
    }
}

// ---------------- launcher ----------------
extern "C" void kernel_launch(void* const* d_in, const int* in_sizes, int n_in,
                              void* d_out, int out_size)
{
    const float* x  = (const float*)d_in[0];
    const float* wq = (const float*)d_in[1];
    const float* bq = (const float*)d_in[2];
    const float* wk = (const float*)d_in[3];
    const float* bk = (const float*)d_in[4];
    const float* wv = (const float*)d_in[5];
    const float* bv = (const float*)d_in[6];
    const float* wz = (const float*)d_in[7];
    const float* bz = (const float*)d_in[8];
    float* out = (float*)d_out;

    const int SM_PROJ = (8192 + 64*129) * 4;   // 65792 B

    cudaFuncSetAttribute(k_qkv,  cudaFuncAttributeMaxDynamicSharedMemorySize, SM_PROJ);
    cudaFuncSetAttribute(k_attn, cudaFuncAttributeMaxDynamicSharedMemorySize, ATTN_SMEM);
    cudaFuncSetAttribute(k_out,  cudaFuncAttributeMaxDynamicSharedMemorySize, SM_PROJ);

    k_qkv <<<dim3(32, 4, 3), 256, SM_PROJ>>>(x, wq, bq, wk, bk, wv, bv);
    k_attn<<<dim3(32, 4),    256, ATTN_SMEM>>>();
    k_out <<<dim3(32, 4, 2), 256, SM_PROJ>>>(x, wz, bz, out);
}

// round 4
// speedup vs baseline: 6.4791x; 1.3141x over previous
#include <cuda_runtime.h>
#include <cuda_bf16.h>
#include <cstdint>

#define HW   4096
#define CIN  256
#define CMID 128
#define NB   4

// ---------------- scratch ----------------
__device__ __nv_bfloat16 g_qT[NB*HW*CMID];   // [n][t][c]
__device__ __nv_bfloat16 g_kT[NB*HW*CMID];   // [n][s][c]
__device__ __nv_bfloat16 g_vT[NB*HW*CMID];   // [n][s][c]
__device__ __nv_bfloat16 g_zT[NB*HW*CMID];   // [n][t][c]

// ---------------- threefry2x32 (JAX partitionable) ----------------
__device__ __forceinline__ uint32_t thf_bits(uint32_t f) {
    const uint32_t K0 = 0u;
    const uint32_t K1 = 42u;
    const uint32_t K2 = 0x1BD11BDAu ^ 42u;
    uint32_t x0 = 0u + K0;
    uint32_t x1 = f  + K1;
#define THF_R(r) { x0 += x1; x1 = __funnelshift_l(x1, x1, (r)); x1 ^= x0; }
    THF_R(13) THF_R(15) THF_R(26) THF_R(6)   x0 += K1; x1 += K2 + 1u;
    THF_R(17) THF_R(29) THF_R(16) THF_R(24)  x0 += K2; x1 += K0 + 2u;
    THF_R(13) THF_R(15) THF_R(26) THF_R(6)   x0 += K0; x1 += K1 + 3u;
    THF_R(17) THF_R(29) THF_R(16) THF_R(24)  x0 += K1; x1 += K2 + 4u;
    THF_R(13) THF_R(15) THF_R(26) THF_R(6)   x0 += K2; x1 += K0 + 5u;
#undef THF_R
    return x0 ^ x1;
}
// mask <=> (bits>>9) < 838861  <=>  bits < 838861*512
#define MASK_THRESH 429496832u

// ---------------- helpers ----------------
__device__ __forceinline__ void cp16(void* dst, const void* src) {
    uint32_t d = (uint32_t)__cvta_generic_to_shared(dst);
    asm volatile("cp.async.cg.shared.global [%0], [%1], 16;\n" :: "r"(d), "l"(src));
}
__device__ __forceinline__ void ldsm_x4(uint32_t& a0, uint32_t& a1, uint32_t& a2, uint32_t& a3, const void* p) {
    uint32_t s = (uint32_t)__cvta_generic_to_shared(p);
    asm volatile("ldmatrix.sync.aligned.m8n8.x4.shared.b16 {%0,%1,%2,%3}, [%4];\n"
                 : "=r"(a0), "=r"(a1), "=r"(a2), "=r"(a3) : "r"(s));
}
__device__ __forceinline__ void ldsm_x2(uint32_t& b0, uint32_t& b1, const void* p) {
    uint32_t s = (uint32_t)__cvta_generic_to_shared(p);
    asm volatile("ldmatrix.sync.aligned.m8n8.x2.shared.b16 {%0,%1}, [%2];\n"
                 : "=r"(b0), "=r"(b1) : "r"(s));
}
__device__ __forceinline__ void ldsm_x2t(uint32_t& b0, uint32_t& b1, const void* p) {
    uint32_t s = (uint32_t)__cvta_generic_to_shared(p);
    asm volatile("ldmatrix.sync.aligned.m8n8.x2.trans.shared.b16 {%0,%1}, [%2];\n"
                 : "=r"(b0), "=r"(b1) : "r"(s));
}
__device__ __forceinline__ void mma16816(float* d, uint32_t a0, uint32_t a1, uint32_t a2, uint32_t a3,
                                         uint32_t b0, uint32_t b1) {
    asm volatile("mma.sync.aligned.m16n8k16.row.col.f32.bf16.bf16.f32 "
                 "{%0,%1,%2,%3}, {%4,%5,%6,%7}, {%8,%9}, {%0,%1,%2,%3};\n"
                 : "+f"(d[0]), "+f"(d[1]), "+f"(d[2]), "+f"(d[3])
                 : "r"(a0), "r"(a1), "r"(a2), "r"(a3), "r"(b0), "r"(b1));
}
__device__ __forceinline__ uint32_t pack_bf2(float lo, float hi) {
    __nv_bfloat162 h = __floats2bfloat162_rn(lo, hi);
    return *(uint32_t*)&h;
}

// ---------------- kernel 1: q/k/v projection (tensor core) ----------------
// block 256 (8 warps), t-tile 128, grid (32 t, 4 n). All 3 mats per block.
#define QKV_SMEM 135168
__global__ void __launch_bounds__(256, 1)
k_qkv(const float* __restrict__ x,
      const float* __restrict__ wq, const float* __restrict__ bq,
      const float* __restrict__ wk, const float* __restrict__ bk,
      const float* __restrict__ wv, const float* __restrict__ bv)
{
    extern __shared__ char sm8[];
    __nv_bfloat16* Xs = (__nv_bfloat16*)sm8;              // [128 t][264 c]
    __nv_bfloat16* Ws = (__nv_bfloat16*)(sm8 + 67584);    // [128 o][264 c] / reuse as stage [128][136]

    const int tid = threadIdx.x, lane = tid & 31, wid = tid >> 5;
    const int t0 = blockIdx.x * 128, n = blockIdx.y;
    const int g = lane >> 2, tg = lane & 3;

    // load x tile [256 c][128 t] fp32 -> Xs[t][c] bf16 (transpose+convert)
    for (int i = tid; i < 256*32; i += 256) {
        int c = i >> 5, t4 = (i & 31) * 4;
        float4 v = *(const float4*)(x + (size_t)(n*CIN + c)*HW + t0 + t4);
        Xs[(t4+0)*264 + c] = __float2bfloat16(v.x);
        Xs[(t4+1)*264 + c] = __float2bfloat16(v.y);
        Xs[(t4+2)*264 + c] = __float2bfloat16(v.z);
        Xs[(t4+3)*264 + c] = __float2bfloat16(v.w);
    }

#pragma unroll 1
    for (int m = 0; m < 3; m++) {
        const float* wp = (m == 0) ? wq : (m == 1) ? wk : wv;
        const float* bp = (m == 0) ? bq : (m == 1) ? bk : bv;
        __syncthreads();   // Xs ready (iter0) / stage region free
        // load w [128 o][256 c] fp32 -> Ws bf16
        for (int i = tid; i < 128*64; i += 256) {
            int o = i >> 6, c4 = (i & 63) * 4;
            float4 v = *(const float4*)(wp + o*CIN + c4);
            Ws[o*264 + c4 + 0] = __float2bfloat16(v.x);
            Ws[o*264 + c4 + 1] = __float2bfloat16(v.y);
            Ws[o*264 + c4 + 2] = __float2bfloat16(v.z);
            Ws[o*264 + c4 + 3] = __float2bfloat16(v.w);
        }
        __syncthreads();

        float acc[16][4];
#pragma unroll
        for (int j = 0; j < 16; j++)
#pragma unroll
            for (int q = 0; q < 4; q++) acc[j][q] = 0.f;

#pragma unroll
        for (int kk = 0; kk < 16; kk++) {
            uint32_t a0, a1, a2, a3;
            ldsm_x4(a0, a1, a2, a3, Xs + (wid*16 + (lane & 15))*264 + kk*16 + (lane >> 4)*8);
#pragma unroll
            for (int j = 0; j < 16; j++) {
                uint32_t b0, b1;
                ldsm_x2(b0, b1, Ws + (j*8 + (lane & 7))*264 + kk*16 + ((lane >> 3) & 1)*8);
                mma16816(acc[j], a0, a1, a2, a3, b0, b1);
            }
        }
        __syncthreads();   // done reading Ws

        // stage biased bf16 result [t][o] into Ws area, then coalesced store
        __nv_bfloat16* Tb = Ws;   // [128][136]
#pragma unroll
        for (int j = 0; j < 16; j++) {
            int o = j*8 + tg*2;
            float b0 = __ldg(bp + o), b1 = __ldg(bp + o + 1);
            Tb[(wid*16 + g)*136 + o]       = __float2bfloat16(acc[j][0] + b0);
            Tb[(wid*16 + g)*136 + o + 1]   = __float2bfloat16(acc[j][1] + b1);
            Tb[(wid*16 + g + 8)*136 + o]     = __float2bfloat16(acc[j][2] + b0);
            Tb[(wid*16 + g + 8)*136 + o + 1] = __float2bfloat16(acc[j][3] + b1);
        }
        __syncthreads();
        __nv_bfloat16* gdst = (m == 0) ? g_qT : (m == 1) ? g_kT : g_vT;
        for (int i = tid; i < 128*16; i += 256) {
            int r = i >> 4, ch = i & 15;
            *(uint4*)(gdst + (size_t)(n*HW + t0 + r)*CMID + ch*8) =
                *(const uint4*)(Tb + r*136 + ch*8);
        }
    }
}

// ---------------- kernel 2: tensor-core attention, s-tile 128 ----------------
// block 256 (8 warps x 16 t-rows), t-tile 128, grid (32, 4)
#define ATTN_SMEM 174080
__global__ void __launch_bounds__(256, 1)
k_attn()
{
    extern __shared__ char sm8[];
    __nv_bfloat16* Qs  = (__nv_bfloat16*)sm8;               // [128][136]
    __nv_bfloat16* Kb0 = (__nv_bfloat16*)(sm8 + 34816);     // [128][136]
    __nv_bfloat16* Kb1 = (__nv_bfloat16*)(sm8 + 69632);
    __nv_bfloat16* Vb0 = (__nv_bfloat16*)(sm8 + 104448);
    __nv_bfloat16* Vb1 = (__nv_bfloat16*)(sm8 + 139264);

    const int tid = threadIdx.x, lane = tid & 31, wid = tid >> 5;
    const int t0 = blockIdx.x * 128, n = blockIdx.y;
    const int g = lane >> 2, tg = lane & 3;

    // Q tile + s-tile 0
    for (int i = tid; i < 128*16; i += 256) {
        int r = i >> 4, ch = i & 15;
        size_t go = (size_t)(n*HW + r)*CMID + ch*8;
        cp16(Qs  + r*136 + ch*8, g_qT + (size_t)(n*HW + t0 + r)*CMID + ch*8);
        cp16(Kb0 + r*136 + ch*8, g_kT + go);
        cp16(Vb0 + r*136 + ch*8, g_vT + go);
    }
    asm volatile("cp.async.commit_group;\n");

    float Z[16][4];
#pragma unroll
    for (int jc = 0; jc < 16; jc++)
#pragma unroll
        for (int q = 0; q < 4; q++) Z[jc][q] = 0.f;
    float dsum0 = 0.f, dsum1 = 0.f;

#pragma unroll 1
    for (int it = 0; it < 32; it++) {
        const __nv_bfloat16* K_ = (it & 1) ? Kb1 : Kb0;
        const __nv_bfloat16* V_ = (it & 1) ? Vb1 : Vb0;
        if (it + 1 < 32) {
            __nv_bfloat16* Kn = ((it+1) & 1) ? Kb1 : Kb0;
            __nv_bfloat16* Vn = ((it+1) & 1) ? Vb1 : Vb0;
            int s0n = (it + 1) * 128;
            for (int i = tid; i < 128*16; i += 256) {
                int r = i >> 4, ch = i & 15;
                size_t go = (size_t)(n*HW + s0n + r)*CMID + ch*8;
                cp16(Kn + r*136 + ch*8, g_kT + go);
                cp16(Vn + r*136 + ch*8, g_vT + go);
            }
            asm volatile("cp.async.commit_group;\n");
            asm volatile("cp.async.wait_group 1;\n");
        } else {
            asm volatile("cp.async.wait_group 0;\n");
        }
        __syncthreads();

        // ---- GEMM1: S[16t x 128s] ----
        float S[16][4];
#pragma unroll
        for (int j = 0; j < 16; j++)
#pragma unroll
            for (int q = 0; q < 4; q++) S[j][q] = 0.f;
#pragma unroll
        for (int kk = 0; kk < 8; kk++) {
            uint32_t a0, a1, a2, a3;
            ldsm_x4(a0, a1, a2, a3, Qs + (wid*16 + (lane & 15))*136 + kk*16 + (lane >> 4)*8);
#pragma unroll
            for (int j = 0; j < 16; j++) {
                uint32_t b0, b1;
                ldsm_x2(b0, b1, K_ + (j*8 + (lane & 7))*136 + kk*16 + ((lane >> 3) & 1)*8);
                mma16816(S[j], a0, a1, a2, a3, b0, b1);
            }
        }

        // ---- mask (threefry) + exp ----
        const int s0 = it * 128;
        const uint32_t fb0 = ((uint32_t)n << 24) + (uint32_t)(t0 + wid*16 + g)*4096u
                           + (uint32_t)(s0 + tg*2);
        const uint32_t fb1 = fb0 + 8u*4096u;
#pragma unroll
        for (int j = 0; j < 16; j++) {
            uint32_t f0 = fb0 + (uint32_t)(j*8);
            uint32_t f1 = fb1 + (uint32_t)(j*8);
            S[j][0] = (thf_bits(f0)    < MASK_THRESH) ? 0.f : __expf(S[j][0]*0.015625f);
            S[j][1] = (thf_bits(f0+1u) < MASK_THRESH) ? 0.f : __expf(S[j][1]*0.015625f);
            S[j][2] = (thf_bits(f1)    < MASK_THRESH) ? 0.f : __expf(S[j][2]*0.015625f);
            S[j][3] = (thf_bits(f1+1u) < MASK_THRESH) ? 0.f : __expf(S[j][3]*0.015625f);
            dsum0 += S[j][0] + S[j][1];
            dsum1 += S[j][2] + S[j][3];
        }

        // ---- GEMM2: Z[16t x 128c] += P * V ----
#pragma unroll
        for (int m = 0; m < 8; m++) {
            uint32_t pa0 = pack_bf2(S[2*m][0],   S[2*m][1]);
            uint32_t pa1 = pack_bf2(S[2*m][2],   S[2*m][3]);
            uint32_t pa2 = pack_bf2(S[2*m+1][0], S[2*m+1][1]);
            uint32_t pa3 = pack_bf2(S[2*m+1][2], S[2*m+1][3]);
#pragma unroll
            for (int jc = 0; jc < 16; jc++) {
                uint32_t b0, b1;
                ldsm_x2t(b0, b1, V_ + (m*16 + (lane & 7) + ((lane >> 3) & 1)*8)*136 + jc*8);
                mma16816(Z[jc], pa0, pa1, pa2, pa3, b0, b1);
            }
        }
        __syncthreads();
    }

    // ---- row denominators (quad reduce) ----
    dsum0 += __shfl_xor_sync(0xffffffffu, dsum0, 1);
    dsum0 += __shfl_xor_sync(0xffffffffu, dsum0, 2);
    dsum1 += __shfl_xor_sync(0xffffffffu, dsum1, 1);
    dsum1 += __shfl_xor_sync(0xffffffffu, dsum1, 2);
    const float inv0 = 1.f / dsum0, inv1 = 1.f / dsum1;

    // ---- stage zT[t][c] bf16, coalesced store ----
    __nv_bfloat16* Tb = Kb0;   // [128][136]
#pragma unroll
    for (int jc = 0; jc < 16; jc++) {
        int c = jc*8 + tg*2;
        Tb[(wid*16 + g)*136 + c]       = __float2bfloat16(Z[jc][0] * inv0);
        Tb[(wid*16 + g)*136 + c + 1]   = __float2bfloat16(Z[jc][1] * inv0);
        Tb[(wid*16 + g + 8)*136 + c]     = __float2bfloat16(Z[jc][2] * inv1);
        Tb[(wid*16 + g + 8)*136 + c + 1] = __float2bfloat16(Z[jc][3] * inv1);
    }
    __syncthreads();
    for (int i = tid; i < 128*16; i += 256) {
        int r = i >> 4, ch = i & 15;
        *(uint4*)(g_zT + (size_t)(n*HW + t0 + r)*CMID + ch*8) =
            *(const uint4*)(Tb + r*136 + ch*8);
    }
}

// ---------------- kernel 3: output projection + residual (tensor core) ----------------
// block 256, o-tile 128, t-tile 128, grid (32 t, 4 n, 2 o)
#define OUT_SMEM 69632
__global__ void __launch_bounds__(256, 1)
k_out(const float* __restrict__ x, const float* __restrict__ wz,
      const float* __restrict__ bz, float* __restrict__ out)
{
    extern __shared__ char sm8[];
    __nv_bfloat16* Wzs = (__nv_bfloat16*)sm8;               // [128 o][136 c]
    __nv_bfloat16* Zts = (__nv_bfloat16*)(sm8 + 34816);     // [128 t][136 c]
    float*         Os  = (float*)sm8;                        // reuse: [128 o][132 t] fp32

    const int tid = threadIdx.x, lane = tid & 31, wid = tid >> 5;
    const int t0 = blockIdx.x * 128, n = blockIdx.y, o0 = blockIdx.z * 128;
    const int g = lane >> 2, tg = lane & 3;

    // load wz tile fp32 -> bf16
    for (int i = tid; i < 128*32; i += 256) {
        int o = i >> 5, c4 = (i & 31) * 4;
        float4 v = *(const float4*)(wz + (size_t)(o0 + o)*CMID + c4);
        Wzs[o*136 + c4 + 0] = __float2bfloat16(v.x);
        Wzs[o*136 + c4 + 1] = __float2bfloat16(v.y);
        Wzs[o*136 + c4 + 2] = __float2bfloat16(v.z);
        Wzs[o*136 + c4 + 3] = __float2bfloat16(v.w);
    }
    // load zT tile bf16 (straight copy)
    for (int i = tid; i < 128*16; i += 256) {
        int r = i >> 4, ch = i & 15;
        *(uint4*)(Zts + r*136 + ch*8) =
            *(const uint4*)(g_zT + (size_t)(n*HW + t0 + r)*CMID + ch*8);
    }
    __syncthreads();

    float acc[16][4];
#pragma unroll
    for (int j = 0; j < 16; j++)
#pragma unroll
        for (int q = 0; q < 4; q++) acc[j][q] = 0.f;

#pragma unroll
    for (int kk = 0; kk < 8; kk++) {
        uint32_t a0, a1, a2, a3;
        ldsm_x4(a0, a1, a2, a3, Wzs + (wid*16 + (lane & 15))*136 + kk*16 + (lane >> 4)*8);
#pragma unroll
        for (int j = 0; j < 16; j++) {
            uint32_t b0, b1;
            ldsm_x2(b0, b1, Zts + (j*8 + (lane & 7))*136 + kk*16 + ((lane >> 3) & 1)*8);
            mma16816(acc[j], a0, a1, a2, a3, b0, b1);
        }
    }
    __syncthreads();   // done with Wzs/Zts, reuse as Os

    // stage fp32 [o][t]
#pragma unroll
    for (int j = 0; j < 16; j++) {
        int t = j*8 + tg*2;
        Os[(wid*16 + g)*132 + t]       = acc[j][0];
        Os[(wid*16 + g)*132 + t + 1]   = acc[j][1];
        Os[(wid*16 + g + 8)*132 + t]     = acc[j][2];
        Os[(wid*16 + g + 8)*132 + t + 1] = acc[j][3];
    }
    __syncthreads();

    // out = x + bz + Os, coalesced along t
    for (int i = tid; i < 128*32; i += 256) {
        int o = i >> 5, t4 = (i & 31) * 4;
        size_t base = (size_t)(n*CIN + o0 + o)*HW + t0 + t4;
        float bb = __ldg(bz + o0 + o);
        float4 xv = *(const float4*)(x + base);
        float4 r;
        r.x = xv.x + bb + Os[o*132 + t4 + 0];
        r.y = xv.y + bb + Os[o*132 + t4 + 1];
        r.z = xv.z + bb + Os[o*132 + t4 + 2];
        r.w = xv.w + bb + Os[o*132 + t4 + 3];
        *(float4*)(out + base) = r;
    }
}

// ---------------- launcher ----------------
extern "C" void kernel_launch(void* const* d_in, const int* in_sizes, int n_in,
                              void* d_out, int out_size)
{
    const float* x  = (const float*)d_in[0];
    const float* wq = (const float*)d_in[1];
    const float* bq = (const float*)d_in[2];
    const float* wk = (const float*)d_in[3];
    const float* bk = (const float*)d_in[4];
    const float* wv = (const float*)d_in[5];
    const float* bv = (const float*)d_in[6];
    const float* wz = (const float*)d_in[7];
    const float* bz = (const float*)d_in[8];
    float* out = (float*)d_out;

    cudaFuncSetAttribute(k_qkv,  cudaFuncAttributeMaxDynamicSharedMemorySize, QKV_SMEM);
    cudaFuncSetAttribute(k_attn, cudaFuncAttributeMaxDynamicSharedMemorySize, ATTN_SMEM);
    cudaFuncSetAttribute(k_out,  cudaFuncAttributeMaxDynamicSharedMemorySize, OUT_SMEM);

    k_qkv <<<dim3(32, 4),    256, QKV_SMEM>>>(x, wq, bq, wk, bk, wv, bv);
    k_attn<<<dim3(32, 4),    256, ATTN_SMEM>>>();
    k_out <<<dim3(32, 4, 2), 256, OUT_SMEM>>>(x, wz, bz, out);
}